// round 16
// baseline (speedup 1.0000x reference)
#include <cuda_runtime.h>
#include <cuda_bf16.h>
#include <math.h>

// Problem constants
#define NROW 384          // N = 2*bs
#define BSZ  192
#define DIM  1024
#define NM1  383          // N-1
#define MDEN 56328576.0   // N*(N-1)^2
#define TK   48           // gram tile
#define NT   8            // tiles per side (384/48)
#define SROW 70           // smem row stride (floats): conflict-free f32x2 reads
#define NGRAM 144         // gram blocks (36 tile-pairs * 4 k-slices)

// Scratch (device globals; no allocation allowed)
__device__ float g_d[4][NROW * NROW];   // per-kz partial dot planes
__device__ float g_sqp[4 * NROW];       // per-kz partial squared norms
__device__ float g_row[NROW];
__device__ int   g_cnt;                 // zero-init; last block resets -> replay-safe
__device__ int   g_done;                // gram-completion counter; reset by last row block

__device__ __forceinline__ const float* frow(const float* f, int r) {
    return f + (r < BSZ ? r * (2 * DIM) : (r - BSZ) * (2 * DIM) + DIM);
}

// ---- packed f32x2 helpers ----
__device__ __forceinline__ unsigned long long pk2(float lo, float hi) {
    unsigned long long r;
    asm("mov.b64 %0, {%1, %2};" : "=l"(r) : "f"(lo), "f"(hi));
    return r;
}
__device__ __forceinline__ unsigned long long add2(unsigned long long a, unsigned long long b) {
    unsigned long long r;
    asm("add.rn.f32x2 %0, %1, %2;" : "=l"(r) : "l"(a), "l"(b));
    return r;
}
__device__ __forceinline__ unsigned long long fma2p(unsigned long long a, unsigned long long b,
                                                    unsigned long long c) {
    unsigned long long r;
    asm("fma.rn.f32x2 %0, %1, %2, %3;" : "=l"(r) : "l"(a), "l"(b), "l"(c));
    return r;
}
__device__ __forceinline__ unsigned long long abs2(unsigned long long a) {
    return a & 0x7FFFFFFF7FFFFFFFULL;
}
__device__ __forceinline__ float lanesum(unsigned long long a) {
    float lo, hi;
    asm("mov.b64 {%0, %1}, %2;" : "=f"(lo), "=f"(hi) : "l"(a));
    return lo + hi;
}

// block reduces over 8 warps (256 threads); inactive threads pass zeros
__device__ __forceinline__ float2 bred2(float2 v, float2* buf, int tid) {
    int lane = tid & 31, wid = tid >> 5;
    #pragma unroll
    for (int o = 16; o > 0; o >>= 1) {
        v.x += __shfl_xor_sync(0xffffffffu, v.x, o);
        v.y += __shfl_xor_sync(0xffffffffu, v.y, o);
    }
    if (lane == 0) buf[wid] = v;
    __syncthreads();
    if (tid < 8) {
        float2 w = buf[tid];
        #pragma unroll
        for (int o = 4; o > 0; o >>= 1) {
            w.x += __shfl_xor_sync(0xffu, w.x, o);
            w.y += __shfl_xor_sync(0xffu, w.y, o);
        }
        if (tid == 0) buf[0] = w;
    }
    __syncthreads();
    float2 r = buf[0];
    __syncthreads();
    return r;
}

__device__ __forceinline__ float4 bred4(float4 v, float4* buf, int tid) {
    int lane = tid & 31, wid = tid >> 5;
    #pragma unroll
    for (int o = 16; o > 0; o >>= 1) {
        v.x += __shfl_xor_sync(0xffffffffu, v.x, o);
        v.y += __shfl_xor_sync(0xffffffffu, v.y, o);
        v.z += __shfl_xor_sync(0xffffffffu, v.z, o);
        v.w += __shfl_xor_sync(0xffffffffu, v.w, o);
    }
    if (lane == 0) buf[wid] = v;
    __syncthreads();
    if (tid < 8) {
        float4 w = buf[tid];
        #pragma unroll
        for (int o = 4; o > 0; o >>= 1) {
            w.x += __shfl_xor_sync(0xffu, w.x, o);
            w.y += __shfl_xor_sync(0xffu, w.y, o);
            w.z += __shfl_xor_sync(0xffu, w.z, o);
            w.w += __shfl_xor_sync(0xffu, w.w, o);
        }
        if (tid == 0) buf[0] = w;
    }
    __syncthreads();
    float4 r = buf[0];
    __syncthreads();
    return r;
}

// ---------------------------------------------------------------------------
// Fused kernel: blocks [0,144) = gram (k-split symmetric tiles, f32x2 FMA,
// register-prefetch pipeline); blocks [144,528) = per-row loss. Row blocks do
// all label-only work (histogram/ranks/sort positions) BEFORE waiting on the
// gram-completion counter, overlapping it with gram execution.
// Deadlock-free: in-order dispatch + >=2 blocks/SM resident (296 slots) means
// all 144 gram blocks are in wave 1 and never wait.
// ---------------------------------------------------------------------------
__global__ __launch_bounds__(256, 2) void fused_kernel(const float* __restrict__ feats,
                                                       const int* __restrict__ labels,
                                                       float* __restrict__ out) {
    __shared__ __align__(16) char sm[27648];
    int tid = threadIdx.x;

    if (blockIdx.x < NGRAM) {
        // ================= GRAM PART =================
        float (*As)[SROW] = (float(*)[SROW])sm;
        float (*Bs)[SROW] = (float(*)[SROW])(sm + TK * SROW * 4);

        int bid = blockIdx.x;
        int p = bid >> 2, kz = bid & 3;
        int a = 0, rem = p;
        while (rem >= NT - a) { rem -= NT - a; a++; }
        int b = a + rem;

        int ty = tid >> 4, tx = tid & 15;
        int r0 = a * TK, c0 = b * TK;
        int kbase = kz * 256;

        int rr[3], kk4[3];
        const float* ap[3];
        const float* bp[3];
        #pragma unroll
        for (int it = 0; it < 3; it++) {
            int q = tid + it * 256;
            rr[it] = q >> 4;
            kk4[it] = (q & 15) << 2;
            ap[it] = frow(feats, r0 + rr[it]) + kk4[it];
            bp[it] = frow(feats, c0 + rr[it]) + kk4[it];
        }

        float4 av[3], bv[3], av2[3], bv2[3];
        #pragma unroll
        for (int it = 0; it < 3; it++) {
            av[it] = *(const float4*)(ap[it] + kbase);
            bv[it] = *(const float4*)(bp[it] + kbase);
        }

        unsigned long long acc[3][3] = {{0ull,0ull,0ull},{0ull,0ull,0ull},{0ull,0ull,0ull}};

        #pragma unroll
        for (int ch = 0; ch < 4; ch++) {
            #pragma unroll
            for (int it = 0; it < 3; it++) {
                *(float2*)&As[rr[it]][kk4[it]]     = make_float2(av[it].x, av[it].y);
                *(float2*)&As[rr[it]][kk4[it] + 2] = make_float2(av[it].z, av[it].w);
                *(float2*)&Bs[rr[it]][kk4[it]]     = make_float2(bv[it].x, bv[it].y);
                *(float2*)&Bs[rr[it]][kk4[it] + 2] = make_float2(bv[it].z, bv[it].w);
            }
            __syncthreads();
            if (ch < 3) {
                int kc = kbase + (ch + 1) * 64;
                #pragma unroll
                for (int it = 0; it < 3; it++) {
                    av2[it] = *(const float4*)(ap[it] + kc);
                    bv2[it] = *(const float4*)(bp[it] + kc);
                }
            }
            const unsigned long long* a0p = (const unsigned long long*)&As[3 * ty + 0][0];
            const unsigned long long* a1p = (const unsigned long long*)&As[3 * ty + 1][0];
            const unsigned long long* a2p = (const unsigned long long*)&As[3 * ty + 2][0];
            const unsigned long long* b0p = (const unsigned long long*)&Bs[3 * tx + 0][0];
            const unsigned long long* b1p = (const unsigned long long*)&Bs[3 * tx + 1][0];
            const unsigned long long* b2p = (const unsigned long long*)&Bs[3 * tx + 2][0];
            #pragma unroll
            for (int kk = 0; kk < 32; kk++) {
                unsigned long long a0 = a0p[kk], a1 = a1p[kk], a2 = a2p[kk];
                unsigned long long b0 = b0p[kk], b1 = b1p[kk], b2 = b2p[kk];
                acc[0][0] = fma2p(a0, b0, acc[0][0]);
                acc[0][1] = fma2p(a0, b1, acc[0][1]);
                acc[0][2] = fma2p(a0, b2, acc[0][2]);
                acc[1][0] = fma2p(a1, b0, acc[1][0]);
                acc[1][1] = fma2p(a1, b1, acc[1][1]);
                acc[1][2] = fma2p(a1, b2, acc[1][2]);
                acc[2][0] = fma2p(a2, b0, acc[2][0]);
                acc[2][1] = fma2p(a2, b1, acc[2][1]);
                acc[2][2] = fma2p(a2, b2, acc[2][2]);
            }
            __syncthreads();
            if (ch < 3) {
                #pragma unroll
                for (int it = 0; it < 3; it++) { av[it] = av2[it]; bv[it] = bv2[it]; }
            }
        }

        #pragma unroll
        for (int i2 = 0; i2 < 3; i2++) {
            #pragma unroll
            for (int j2 = 0; j2 < 3; j2++) {
                int r = r0 + 3 * ty + i2, c = c0 + 3 * tx + j2;
                float v = lanesum(acc[i2][j2]);
                g_d[kz][r * NROW + c] = v;
                g_d[kz][c * NROW + r] = v;
                if (r == c) g_sqp[kz * NROW + r] = v;
            }
        }
        // release: every thread fences its own stores, then one signals
        __threadfence();
        __syncthreads();
        if (tid == 0) atomicAdd(&g_done, 1);
        return;
    }

    // ================= ROW PART =================
    int i = blockIdx.x - NGRAM;
    float4* ext4 = (float4*)sm;                          // 288*16 = 4608
    float*  zs   = (float*)(sm + 4608);                  // 1536
    float*  bs   = (float*)(sm + 6144);                  // 1536
    short*  gsA  = (short*)(sm + 7680);                  // 768
    short*  geA  = (short*)(sm + 8448);                  // 768
    int*    cntw = (int*)(sm + 9216);                    // 12*52*4 = 2496
    int*    tot  = (int*)(sm + 11712);                   // 208
    int*    basev= (int*)(sm + 11920);                   // 208
    unsigned long long* ymask = (unsigned long long*)(sm + 12128);
    float4* redbuf = (float4*)(sm + 12160);              // 8*16 = 128
    double* dred  = (double*)(sm + 12288);               // 1024
    int*    isLast= (int*)(sm + 13312);

    int lane = tid & 31, wid = tid >> 5;
    bool e0 = tid < 192;
    bool e1 = tid < 191;

    for (int idx = tid; idx < 12 * 52; idx += 256) cntw[idx] = 0;
    if (tid == 0) *ymask = 0ull;
    __syncthreads();

    int labi = labels[i >= BSZ ? i - BSZ : i];

    // ---- phase 1: label-only work (overlaps gram) ----
    int y0 = 0, y1 = 0, jj0 = 0, jj1 = 0;
    unsigned mm0 = 0, mm1 = 0;
    if (e0) {
        jj0 = tid + (tid >= i);
        y0 = abs(labi - labels[jj0 >= BSZ ? jj0 - BSZ : jj0]);
    }
    if (e1) {
        int p1 = tid + 192;
        jj1 = p1 + (p1 >= i);
        y1 = abs(labi - labels[jj1 >= BSZ ? jj1 - BSZ : jj1]);
    }
    if (e0) atomicOr(ymask, (1ull << y0) | (e1 ? (1ull << y1) : 0ull));

    if (e0) {
        mm0 = __match_any_sync(__activemask(), y0);
        if (lane == __ffs(mm0) - 1) atomicAdd(&cntw[wid * 52 + y0], __popc(mm0));
    }
    if (e1) {
        mm1 = __match_any_sync(__activemask(), y1);
        if (lane == __ffs(mm1) - 1) atomicAdd(&cntw[(6 + wid) * 52 + y1], __popc(mm1));
    }
    __syncthreads();   // barrier A: counts + ymask complete

    float bp0 = 0.1f * (float)__popcll(*ymask & ((1ull << y0) - 1ull));
    float bp1 = 0.1f * (float)__popcll(*ymask & ((1ull << y1) - 1ull));

    // in-place: cntw[s][y] -> count in slots < s; tot[y] = total
    if (tid < 52) {
        int run = 0;
        #pragma unroll
        for (int w2 = 0; w2 < 12; w2++) {
            int c = cntw[w2 * 52 + tid];
            cntw[w2 * 52 + tid] = run;
            run += c;
        }
        tot[tid] = run;
    }
    __syncthreads();   // barrier B

    if (tid < 32) {
        int a0 = tot[tid];
        int v = a0;
        #pragma unroll
        for (int o = 1; o < 32; o <<= 1) {
            int n = __shfl_up_sync(0xffffffffu, v, o);
            if (tid >= o) v += n;
        }
        basev[tid] = v - a0;
        int c32 = __shfl_sync(0xffffffffu, v, 31);
        int a1 = (tid < 20) ? tot[32 + tid] : 0;
        int w = a1;
        #pragma unroll
        for (int o = 1; o < 32; o <<= 1) {
            int n = __shfl_up_sync(0xffffffffu, w, o);
            if (tid >= o) w += n;
        }
        if (tid < 20) basev[32 + tid] = c32 + w - a1;
    }
    __syncthreads();   // barrier C

    // positions + b-side writes (z-independent)
    int pos0 = 0, pos1 = 0;
    if (e0) {
        pos0 = basev[y0] + cntw[wid * 52 + y0] + __popc(mm0 & ((1u << lane) - 1u));
        bs[pos0] = bp0;
        gsA[pos0] = (short)basev[y0];
        geA[pos0] = (short)(basev[y0] + tot[y0]);
        int qp = pos0 >> 1;
        if (pos0 & 1) ext4[qp].w = bp0; else ext4[qp].z = bp0;
        if (pos0 <= 192) {
            int qd = (pos0 + NM1) >> 1;
            if (pos0 & 1) ext4[qd].z = bp0; else ext4[qd].w = bp0;
        }
    }
    if (e1) {
        pos1 = basev[y1] + cntw[(6 + wid) * 52 + y1] + __popc(mm1 & ((1u << lane) - 1u));
        bs[pos1] = bp1;
        gsA[pos1] = (short)basev[y1];
        geA[pos1] = (short)(basev[y1] + tot[y1]);
        int qp = pos1 >> 1;
        if (pos1 & 1) ext4[qp].w = bp1; else ext4[qp].z = bp1;
        if (pos1 <= 192) {
            int qd = (pos1 + NM1) >> 1;
            if (pos1 & 1) ext4[qd].z = bp1; else ext4[qd].w = bp1;
        }
    }

    // ---- wait for gram completion ----
    if (tid == 0) {
        while (*((volatile int*)&g_done) < NGRAM) __nanosleep(64);
    }
    __syncthreads();
    __threadfence();

    // ---- phase 2: gather z, write z-side ----
    float z0 = 0.f, z1 = 0.f;
    float sq_i = g_sqp[i] + g_sqp[NROW + i] + g_sqp[2 * NROW + i] + g_sqp[3 * NROW + i];
    if (e0) {
        float dot = g_d[0][i * NROW + jj0] + g_d[1][i * NROW + jj0]
                  + g_d[2][i * NROW + jj0] + g_d[3][i * NROW + jj0];
        float sq_j = g_sqp[jj0] + g_sqp[NROW + jj0] + g_sqp[2 * NROW + jj0] + g_sqp[3 * NROW + jj0];
        z0 = sqrtf(fmaxf(sq_i + sq_j - 2.f * dot, 0.f));
        zs[pos0] = z0;
        int qp = pos0 >> 1;
        if (pos0 & 1) ext4[qp].y = z0; else ext4[qp].x = z0;
        if (pos0 <= 192) {
            int qd = (pos0 + NM1) >> 1;
            if (pos0 & 1) ext4[qd].x = z0; else ext4[qd].y = z0;
        }
    }
    if (e1) {
        float dot = g_d[0][i * NROW + jj1] + g_d[1][i * NROW + jj1]
                  + g_d[2][i * NROW + jj1] + g_d[3][i * NROW + jj1];
        float sq_j = g_sqp[jj1] + g_sqp[NROW + jj1] + g_sqp[2 * NROW + jj1] + g_sqp[3 * NROW + jj1];
        z1 = sqrtf(fmaxf(sq_i + sq_j - 2.f * dot, 0.f));
        zs[pos1] = z1;
        int qp = pos1 >> 1;
        if (pos1 & 1) ext4[qp].y = z1; else ext4[qp].x = z1;
        if (pos1 <= 192) {
            int qd = (pos1 + NM1) >> 1;
            if (pos1 & 1) ext4[qd].x = z1; else ext4[qd].y = z1;
        }
    }
    __syncthreads();   // barrier D: zs/bs/ext4 complete

    // ---- means + variance ----
    float2 s1 = bred2(make_float2((e0 ? z0 : 0.f) + (e1 ? z1 : 0.f),
                                  (e0 ? bp0 : 0.f) + (e1 ? bp1 : 0.f)),
                      (float2*)redbuf, tid);
    float zm = s1.x * (1.0f / (float)NM1);
    float bm = s1.y * (1.0f / (float)NM1);
    float vsum = 0.f;
    if (e0) {
        float dz0 = z0 - zm, db0 = bp0 - bm;
        vsum = dz0 * dz0 + db0 * db0;
    }
    if (e1) {
        float dz1 = z1 - zm, db1 = bp1 - bm;
        vsum += dz1 * dz1 + db1 * db1;
    }

    // ---- cross term: j0=2t, j1=2t+1 over 95 extended pairs [t+1 .. t+95] ----
    float accC = 0.f;
    if (tid <= 190) {
        int t = tid;
        float zj0 = zs[2 * t],     bj0 = bs[2 * t];
        float zj1 = zs[2 * t + 1], bj1 = bs[2 * t + 1];
        unsigned long long nz0 = pk2(-zj0, -zj0), nb0 = pk2(-bj0, -bj0);
        unsigned long long nz1 = pk2(-zj1, -zj1), nb1 = pk2(-bj1, -bj1);
        unsigned long long aA = 0ull, aB = 0ull;
        unsigned int addr = (unsigned int)__cvta_generic_to_shared(&ext4[t + 1]);
        #pragma unroll 5
        for (int q = 0; q < 95; q++) {
            unsigned long long zk2, bk2;
            asm("ld.shared.v2.b64 {%0, %1}, [%2];" : "=l"(zk2), "=l"(bk2) : "r"(addr));
            addr += 16;
            aA = fma2p(abs2(add2(zk2, nz0)), abs2(add2(bk2, nb0)), aA);
            aB = fma2p(abs2(add2(zk2, nz1)), abs2(add2(bk2, nb1)), aB);
        }
        accC = lanesum(aA) + lanesum(aB);
        accC += fabsf((zj1 - zj0) * (bj1 - bj0));
        {
            int ke = 2 * t + 192; if (ke >= NM1) ke -= NM1;
            accC += fabsf((zs[ke] - zj1) * (bs[ke] - bj1));
        }
        accC += fabsf((zs[382] - zs[t]) * (bs[382] - bs[t]));
    }

    // ---- pos correction ----
    float accP = 0.f, accQ = 0.f;
    if (e0) {
        float zj = zs[pos0];
        int g0 = gsA[pos0], g1 = geA[pos0];
        for (int kk = g0; kk < g1; kk++) {
            float d = fabsf(zs[kk] - zj);
            accP += __fdividef(d, 1.0f + __expf(0.1f - d));
            accQ = fmaf(d, d, accQ);
        }
    }
    if (e1) {
        float zj = zs[pos1];
        int g0 = gsA[pos1], g1 = geA[pos1];
        for (int kk = g0; kk < g1; kk++) {
            float d = fabsf(zs[kk] - zj);
            accP += __fdividef(d, 1.0f + __expf(0.1f - d));
            accQ = fmaf(d, d, accQ);
        }
    }

    float4 s2 = bred4(make_float4(vsum, accC, accP, accQ), redbuf, tid);

    if (tid == 0) {
        float total = (2.0f * (float)NM1) * s2.x - 4.0f * s2.y + s2.z - s2.w;
        g_row[i] = total;
    }

    // ---- fused final reduction ----
    if (tid == 0) {
        __threadfence();
        int old = atomicAdd(&g_cnt, 1);
        *isLast = (old == NROW - 1);
    }
    __syncthreads();
    if (*isLast) {
        if (tid < 128) {
            dred[tid] = (double)g_row[tid] + (double)g_row[tid + 128]
                      + (double)g_row[tid + 256];
        }
        __syncthreads();
        #pragma unroll
        for (int st = 64; st > 0; st >>= 1) {
            if (tid < st) dred[tid] += dred[tid + st];
            __syncthreads();
        }
        if (tid == 0) {
            out[0] = (float)(dred[0] / MDEN);
            g_cnt = 0;                          // reset for graph replay
            g_done = 0;
        }
    }
}

// ---------------------------------------------------------------------------
extern "C" void kernel_launch(void* const* d_in, const int* in_sizes, int n_in,
                              void* d_out, int out_size) {
    const float* features = (const float*)d_in[0];   // [192, 2, 1024] f32
    const int*   labels   = (const int*)d_in[1];     // [192, 1] i32
    (void)in_sizes; (void)n_in; (void)out_size;      // d_in[2] (ranks) unused

    fused_kernel<<<NGRAM + NROW, 256>>>(features, labels, (float*)d_out);
}